// round 6
// baseline (speedup 1.0000x reference)
#include <cuda_runtime.h>
#include <cuda_bf16.h>

// DeepFilter: 5-tap complex FIR over first 256 freq bins + passthrough of the rest.
// spec:  [B=8][2][T=4096][F=481]  fp32
// coefs: [B=8][10][T=4096][256]   fp32   (10 = {real taps 0..4, imag taps 0..4})
// out:   [B=8][2][T=4096][F=481]  fp32
//
// Split design:
//  - FIR kernel: thread = freq bin, block = 2 consecutive time steps sharing a
//    6-row spec window in registers (validated R3 core; 32 regs, high occupancy).
//  - Copy kernel: flat streaming copy of the tail region (bins 256..480),
//    8 elems/thread, fully coalesced.

#define NUM_FREQS 256
#define FRAME_SIZE 5
#define B_DIM 8
#define T_DIM 4096
#define F_TOTAL 481
#define F_TAIL (F_TOTAL - NUM_FREQS)   // 225

__global__ __launch_bounds__(256) void deepfilter_fir_kernel(
    const float* __restrict__ spec,
    const float* __restrict__ coefs,
    float* __restrict__ out)
{
    const int b  = blockIdx.y;
    const int t0 = blockIdx.x << 1;          // 2 time steps per block
    const int f  = threadIdx.x;              // 0 .. 255

    const int spec_b0 = (b * 2) * T_DIM * F_TOTAL;     // real channel base
    const int spec_b1 = spec_b0 + T_DIM * F_TOTAL;     // imag channel base

    // Spec window registers: ts = t0-4 .. t0+1  (6 rows, shared by both outputs)
    float pr[6], pi[6];
#pragma unroll
    for (int k = 0; k < 6; ++k) {
        const int ts = t0 - 4 + k;
        if (ts >= 0) {
            const int so = ts * F_TOTAL + f;
            pr[k] = spec[spec_b0 + so];
            pi[k] = spec[spec_b1 + so];
        } else {
            pr[k] = 0.0f;
            pi[k] = 0.0f;
        }
    }

    const int c_row  = ((b * 10) * T_DIM + t0) * NUM_FREQS + f;
    const int c_kstr = T_DIM * NUM_FREQS;    // per-tap stride

    float re0 = 0.f, im0 = 0.f, re1 = 0.f, im1 = 0.f;
#pragma unroll
    for (int k = 0; k < FRAME_SIZE; ++k) {
        const float cr0 = __ldcs(&coefs[c_row + k * c_kstr]);
        const float ci0 = __ldcs(&coefs[c_row + (k + FRAME_SIZE) * c_kstr]);
        const float cr1 = __ldcs(&coefs[c_row + NUM_FREQS + k * c_kstr]);
        const float ci1 = __ldcs(&coefs[c_row + NUM_FREQS + (k + FRAME_SIZE) * c_kstr]);

        re0 = fmaf(pr[k],      cr0, re0);
        re0 = fmaf(-pi[k],     ci0, re0);
        im0 = fmaf(pi[k],      cr0, im0);
        im0 = fmaf(pr[k],      ci0, im0);

        re1 = fmaf(pr[k + 1],  cr1, re1);
        re1 = fmaf(-pi[k + 1], ci1, re1);
        im1 = fmaf(pi[k + 1],  cr1, im1);
        im1 = fmaf(pr[k + 1],  ci1, im1);
    }

    const int orow = t0 * F_TOTAL + f;
    out[spec_b0 + orow]           = re0;
    out[spec_b1 + orow]           = im0;
    out[spec_b0 + orow + F_TOTAL] = re1;
    out[spec_b1 + orow + F_TOTAL] = im1;
}

// Tail copy: bins 256..480 for all (b, ch, t). Total 8*2*4096*225 = 14,745,600
// elems. Flat index -> (row, j) with row = idx/225 spanning (b*2+ch)*4096+t,
// which maps directly onto the contiguous [(b*2+ch)][t][481] layout.
#define TAIL_TOTAL (B_DIM * 2 * T_DIM * F_TAIL)

__global__ __launch_bounds__(256) void deepfilter_copy_kernel(
    const float* __restrict__ spec,
    float* __restrict__ out)
{
    const int base = blockIdx.x * (256 * 8) + threadIdx.x;
#pragma unroll
    for (int u = 0; u < 8; ++u) {
        const unsigned idx = base + u * 256;
        const unsigned row = idx / F_TAIL;          // const-div -> mul/shift
        const unsigned j   = idx - row * F_TAIL;
        const unsigned o   = row * F_TOTAL + NUM_FREQS + j;
        out[o] = __ldcs(&spec[o]);
    }
}

extern "C" void kernel_launch(void* const* d_in, const int* in_sizes, int n_in,
                              void* d_out, int out_size)
{
    const float* spec  = (const float*)d_in[0];
    const float* coefs = (const float*)d_in[1];
    float* out = (float*)d_out;

    dim3 fir_grid(T_DIM / 2, B_DIM);
    deepfilter_fir_kernel<<<fir_grid, 256>>>(spec, coefs, out);

    // 14,745,600 / (256*8) = 7200 blocks, exact coverage.
    deepfilter_copy_kernel<<<TAIL_TOTAL / (256 * 8), 256>>>(spec, out);
}

// round 7
// speedup vs baseline: 1.1679x; 1.1679x over previous
#include <cuda_runtime.h>
#include <cuda_bf16.h>

// DeepFilter: 5-tap complex FIR over first 256 freq bins + passthrough of the rest.
// spec:  [B=8][2][T=4096][F=481]  fp32
// coefs: [B=8][10][T=4096][256]   fp32
// out:   [B=8][2][T=4096][F=481]  fp32
//
// One launch, two block specializations interleaved across the grid:
//  - FIR blocks (16384): thread = freq bin, 2 time steps/block, 6-row spec
//    window in registers (validated R3 core).
//  - Copy blocks (7200): flat streaming copy of tail bins 256..480,
//    8 elems/thread.
// Interleaving (Bresenham over blockIdx) keeps both traffic types flowing
// concurrently so DRAM stays saturated end-to-end (R6 showed a serial copy
// phase runs latency-bound at 2.5 TB/s).

#define NUM_FREQS 256
#define FRAME_SIZE 5
#define B_DIM 8
#define T_DIM 4096
#define F_TOTAL 481
#define F_TAIL (F_TOTAL - NUM_FREQS)        // 225
#define N_FIR_BLK (B_DIM * T_DIM / 2)       // 16384
#define TAIL_TOTAL (B_DIM * 2 * T_DIM * F_TAIL)   // 14,745,600
#define N_CPY_BLK (TAIL_TOTAL / (256 * 8))  // 7200
#define N_TOT_BLK (N_FIR_BLK + N_CPY_BLK)   // 23584

__global__ __launch_bounds__(256) void deepfilter_kernel(
    const float* __restrict__ spec,
    const float* __restrict__ coefs,
    float* __restrict__ out)
{
    const unsigned bx = blockIdx.x;
    // Bresenham split: c_before = number of copy blocks among [0, bx)
    const unsigned c_before = (unsigned)(((unsigned long long)bx * N_CPY_BLK) / N_TOT_BLK);
    const unsigned c_incl   = (unsigned)(((unsigned long long)(bx + 1) * N_CPY_BLK) / N_TOT_BLK);

    if (c_incl == c_before) {
        // ---------------- FIR block ----------------
        const unsigned fir_id = bx - c_before;      // 0 .. 16383
        const int b  = fir_id >> 11;                // 2048 per batch
        const int t0 = (fir_id & 2047) << 1;        // 2 time steps
        const int f  = threadIdx.x;                 // 0 .. 255

        const int spec_b0 = (b * 2) * T_DIM * F_TOTAL;
        const int spec_b1 = spec_b0 + T_DIM * F_TOTAL;

        // Spec window: ts = t0-4 .. t0+1 (6 rows shared by both outputs)
        float pr[6], pi[6];
#pragma unroll
        for (int k = 0; k < 6; ++k) {
            const int ts = t0 - 4 + k;
            if (ts >= 0) {
                const int so = ts * F_TOTAL + f;
                pr[k] = spec[spec_b0 + so];
                pi[k] = spec[spec_b1 + so];
            } else {
                pr[k] = 0.0f;
                pi[k] = 0.0f;
            }
        }

        const int c_row  = ((b * 10) * T_DIM + t0) * NUM_FREQS + f;
        const int c_kstr = T_DIM * NUM_FREQS;

        float re0 = 0.f, im0 = 0.f, re1 = 0.f, im1 = 0.f;
#pragma unroll
        for (int k = 0; k < FRAME_SIZE; ++k) {
            const float cr0 = __ldcs(&coefs[c_row + k * c_kstr]);
            const float ci0 = __ldcs(&coefs[c_row + (k + FRAME_SIZE) * c_kstr]);
            const float cr1 = __ldcs(&coefs[c_row + NUM_FREQS + k * c_kstr]);
            const float ci1 = __ldcs(&coefs[c_row + NUM_FREQS + (k + FRAME_SIZE) * c_kstr]);

            re0 = fmaf(pr[k],      cr0, re0);
            re0 = fmaf(-pi[k],     ci0, re0);
            im0 = fmaf(pi[k],      cr0, im0);
            im0 = fmaf(pr[k],      ci0, im0);

            re1 = fmaf(pr[k + 1],  cr1, re1);
            re1 = fmaf(-pi[k + 1], ci1, re1);
            im1 = fmaf(pi[k + 1],  cr1, im1);
            im1 = fmaf(pr[k + 1],  ci1, im1);
        }

        const int orow = t0 * F_TOTAL + f;
        out[spec_b0 + orow]           = re0;
        out[spec_b1 + orow]           = im0;
        out[spec_b0 + orow + F_TOTAL] = re1;
        out[spec_b1 + orow + F_TOTAL] = im1;
    } else {
        // ---------------- Copy block ----------------
        // copy_id = c_before; covers 2048 tail elems.
        const unsigned base = c_before * (256u * 8u) + threadIdx.x;
#pragma unroll
        for (int u = 0; u < 8; ++u) {
            const unsigned idx = base + u * 256u;
            const unsigned row = idx / F_TAIL;       // const-div -> mul
            const unsigned j   = idx - row * F_TAIL;
            const unsigned o   = row * F_TOTAL + NUM_FREQS + j;
            out[o] = __ldcs(&spec[o]);
        }
    }
}

extern "C" void kernel_launch(void* const* d_in, const int* in_sizes, int n_in,
                              void* d_out, int out_size)
{
    const float* spec  = (const float*)d_in[0];
    const float* coefs = (const float*)d_in[1];
    float* out = (float*)d_out;

    deepfilter_kernel<<<N_TOT_BLK, 256>>>(spec, coefs, out);
}